// round 1
// baseline (speedup 1.0000x reference)
#include <cuda_runtime.h>
#include <cuda_bf16.h>

// Grouped submanifold sparse conv, N=400000, C_IN=C_OUT=64, GROUPS=4, K=27.
// Strategy: warp-per-voxel, skip inactive offsets (uniform branch via ballot/ffs),
// weights staged in padded smem, gathered features via deduplicated LDG.128,
// one-offset-ahead prefetch. Lane l computes output channels {2l, 2l+1}.

#define GROUPS 4
#define KOFF   27
#define CPG    16               // channels per group (in and out)
#define WK     (CPG * CPG)      // 256 floats per (g,k)
#define WG_RAW (KOFF * WK)      // 6912 floats per group
#define PG     (WG_RAW + 16)    // padded group stride: shifts group g by 16 banks
#define SMEM_FLOATS (GROUPS * PG)
#define SMEM_BYTES  (SMEM_FLOATS * 4)

__global__ __launch_bounds__(256, 2)
void subm_conv_kernel(const float* __restrict__ feat,
                      const float* __restrict__ weight,
                      const float* __restrict__ bias,
                      const int* __restrict__ nb,
                      float* __restrict__ out,
                      int N, int chunk)
{
    extern __shared__ float sw[];
    // Stage all weights: sw[g*PG + k*256 + ci*16 + co] = weight[g][k][ci][co]
    for (int i = threadIdx.x; i < GROUPS * WG_RAW; i += blockDim.x) {
        int g = i / WG_RAW;
        int r = i - g * WG_RAW;
        sw[g * PG + r] = weight[i];
    }
    __syncthreads();

    const int lane = threadIdx.x & 31;
    const int warp = (blockIdx.x * blockDim.x + threadIdx.x) >> 5;
    const int g    = lane >> 3;          // group handled by this lane
    const int co0  = (lane & 7) * 2;     // out-channel pair within group
    // global out channels are exactly {2*lane, 2*lane+1}
    const float bx = bias[2 * lane];
    const float by = bias[2 * lane + 1];
    const float* wg = sw + g * PG + co0; // base for this lane's weight column pair

    int v0 = warp * chunk;
    int v1 = v0 + chunk;
    if (v1 > N) v1 = N;

    for (int v = v0; v < v1; v++) {
        // Load this voxel's 27 neighbor indices (coalesced, one per lane)
        int idx_l = -1;
        if (lane < KOFF) idx_l = nb[v * KOFF + lane];
        unsigned act = __ballot_sync(0xffffffffu, idx_l >= 0);

        float accx = bx, accy = by;

        // act is never empty: center offset (k=13) is always self-active.
        int k = __ffs(act) - 1; act &= act - 1;
        int nidx = __shfl_sync(0xffffffffu, idx_l, k);
        const float4* fp = (const float4*)feat + (size_t)nidx * 16 + g * 4;
        float4 fa = fp[0], fb = fp[1], fc = fp[2], fd = fp[3];

        while (true) {
            const bool more = (act != 0);
            int k2 = 0;
            float4 fa2, fb2, fc2, fd2;
            if (more) {  // uniform branch: prefetch next active offset's row
                k2 = __ffs(act) - 1; act &= act - 1;
                int nidx2 = __shfl_sync(0xffffffffu, idx_l, k2);
                const float4* fp2 = (const float4*)feat + (size_t)nidx2 * 16 + g * 4;
                fa2 = fp2[0]; fb2 = fp2[1]; fc2 = fp2[2]; fd2 = fp2[3];
            }

            // acc[co] += sum_ci f[ci] * W[g][k][ci][co], W column pair via LDS.64
            const float2* wp = (const float2*)(wg + k * WK);
            float2 w;
            w = wp[0 * 8];  accx += fa.x * w.x; accy += fa.x * w.y;
            w = wp[1 * 8];  accx += fa.y * w.x; accy += fa.y * w.y;
            w = wp[2 * 8];  accx += fa.z * w.x; accy += fa.z * w.y;
            w = wp[3 * 8];  accx += fa.w * w.x; accy += fa.w * w.y;
            w = wp[4 * 8];  accx += fb.x * w.x; accy += fb.x * w.y;
            w = wp[5 * 8];  accx += fb.y * w.x; accy += fb.y * w.y;
            w = wp[6 * 8];  accx += fb.z * w.x; accy += fb.z * w.y;
            w = wp[7 * 8];  accx += fb.w * w.x; accy += fb.w * w.y;
            w = wp[8 * 8];  accx += fc.x * w.x; accy += fc.x * w.y;
            w = wp[9 * 8];  accx += fc.y * w.x; accy += fc.y * w.y;
            w = wp[10 * 8]; accx += fc.z * w.x; accy += fc.z * w.y;
            w = wp[11 * 8]; accx += fc.w * w.x; accy += fc.w * w.y;
            w = wp[12 * 8]; accx += fd.x * w.x; accy += fd.x * w.y;
            w = wp[13 * 8]; accx += fd.y * w.x; accy += fd.y * w.y;
            w = wp[14 * 8]; accx += fd.z * w.x; accy += fd.z * w.y;
            w = wp[15 * 8]; accx += fd.w * w.x; accy += fd.w * w.y;

            if (!more) break;
            k = k2; fa = fa2; fb = fb2; fc = fc2; fd = fd2;
        }

        float2* op = (float2*)(out + (size_t)v * 64);
        op[lane] = make_float2(accx, accy);
    }
}

extern "C" void kernel_launch(void* const* d_in, const int* in_sizes, int n_in,
                              void* d_out, int out_size)
{
    const float* feat   = (const float*)d_in[0];  // [N, 64]
    const float* weight = (const float*)d_in[1];  // [4, 27, 16, 16]
    const float* bias   = (const float*)d_in[2];  // [64]
    const int*   nb     = (const int*)d_in[3];    // [N, 27]
    float* out = (float*)d_out;

    int N = in_sizes[0] / 64;

    static bool attr_set = false;
    // Setting the attribute is idempotent and enqueues no work; safe under capture.
    cudaFuncSetAttribute(subm_conv_kernel,
                         cudaFuncAttributeMaxDynamicSharedMemorySize, SMEM_BYTES);

    const int blocks = 304;                 // 2 CTAs per SM on 152-SM GB300
    const int threads = 256;
    const int warps = blocks * (threads / 32);
    int chunk = (N + warps - 1) / warps;

    subm_conv_kernel<<<blocks, threads, SMEM_BYTES>>>(feat, weight, bias, nb,
                                                      out, N, chunk);
    (void)attr_set; (void)n_in; (void)out_size;
}

// round 2
// speedup vs baseline: 1.0349x; 1.0349x over previous
#include <cuda_runtime.h>
#include <cuda_bf16.h>

// Grouped submanifold sparse conv, N=400000, C_IN=C_OUT=64, GROUPS=4, K=27.
// R2: 8 voxels per warp with register-cached weights per union-offset.
// The R1 kernel was smem-crossbar bound (each weight element -> one FFMA).
// Here each per-k weight load (32 regs) is reused by every voxel in the
// 8-voxel batch whose k-th neighbor is active (avg reuse ~2.15x), cutting
// LDS weight traffic from ~23.8KB to ~11.1KB per voxel.

#define GROUPS 4
#define KOFF   27
#define CPG    16
#define WK     (CPG * CPG)      // 256 floats per (g,k)
#define WG_RAW (KOFF * WK)      // 6912 floats per group
#define PG     (WG_RAW + 16)    // padded group stride (64B bank shift per group)
#define SMEM_FLOATS (GROUPS * PG)
#define SMEM_BYTES  (SMEM_FLOATS * 4)
#define VPW 8                    // voxels per warp-iteration

__global__ __launch_bounds__(256, 2)
void subm_conv_v8(const float* __restrict__ feat,
                  const float* __restrict__ weight,
                  const float* __restrict__ bias,
                  const int* __restrict__ nb,
                  float* __restrict__ out,
                  int N, int iters_per_warp, int total_iters)
{
    extern __shared__ float sw[];
    for (int i = threadIdx.x; i < GROUPS * WG_RAW; i += blockDim.x) {
        int g = i / WG_RAW;
        int r = i - g * WG_RAW;
        sw[g * PG + r] = weight[i];
    }
    __syncthreads();

    const int lane = threadIdx.x & 31;
    const int gwarp = (blockIdx.x * blockDim.x + threadIdx.x) >> 5;
    const int g    = lane >> 3;
    const int co0  = (lane & 7) * 2;
    const float bx = bias[2 * lane];
    const float by = bias[2 * lane + 1];
    const float* wgbase = sw + g * PG + co0;

    int it0 = gwarp * iters_per_warp;
    int it1 = it0 + iters_per_warp;
    if (it1 > total_iters) it1 = total_iters;

    for (int it = it0; it < it1; ++it) {
        const int vb = it * VPW;

        // Load 8 voxels' neighbor rows (coalesced; lane = offset index).
        int idx[VPW];
        unsigned m[VPW];
        #pragma unroll
        for (int j = 0; j < VPW; ++j) {
            int v = vb + j;
            int id = -1;
            if (lane < KOFF && v < N) id = nb[v * KOFF + lane];
            idx[j] = id;
            m[j] = __ballot_sync(0xffffffffu, id >= 0);
        }

        float2 acc[VPW];
        #pragma unroll
        for (int j = 0; j < VPW; ++j) acc[j] = make_float2(bx, by);

        unsigned uni = 0;
        #pragma unroll
        for (int j = 0; j < VPW; ++j) uni |= m[j];

        while (uni) {
            const int k = __ffs(uni) - 1;
            uni &= uni - 1;

            // Register-cache this offset's weight column pair: w[ci] for our
            // (group, co pair). 16 x LDS.64, conflict-free (2-phase floor).
            const float2* wp = (const float2*)(wgbase + k * WK);
            float2 w0  = wp[0 * 8],  w1  = wp[1 * 8],  w2  = wp[2 * 8],  w3  = wp[3 * 8];
            float2 w4  = wp[4 * 8],  w5  = wp[5 * 8],  w6  = wp[6 * 8],  w7  = wp[7 * 8];
            float2 w8  = wp[8 * 8],  w9  = wp[9 * 8],  w10 = wp[10 * 8], w11 = wp[11 * 8];
            float2 w12 = wp[12 * 8], w13 = wp[13 * 8], w14 = wp[14 * 8], w15 = wp[15 * 8];

            #pragma unroll
            for (int j = 0; j < VPW; ++j) {
                if ((m[j] >> k) & 1u) {   // warp-uniform branch
                    const int ni = __shfl_sync(0xffffffffu, idx[j], k);
                    const float4* fp = (const float4*)feat + (size_t)ni * 16 + g * 4;
                    float4 fa = fp[0], fb = fp[1], fc = fp[2], fd = fp[3];
                    float ax = acc[j].x, ay = acc[j].y;
                    ax += fa.x * w0.x;  ay += fa.x * w0.y;
                    ax += fa.y * w1.x;  ay += fa.y * w1.y;
                    ax += fa.z * w2.x;  ay += fa.z * w2.y;
                    ax += fa.w * w3.x;  ay += fa.w * w3.y;
                    ax += fb.x * w4.x;  ay += fb.x * w4.y;
                    ax += fb.y * w5.x;  ay += fb.y * w5.y;
                    ax += fb.z * w6.x;  ay += fb.z * w6.y;
                    ax += fb.w * w7.x;  ay += fb.w * w7.y;
                    ax += fc.x * w8.x;  ay += fc.x * w8.y;
                    ax += fc.y * w9.x;  ay += fc.y * w9.y;
                    ax += fc.z * w10.x; ay += fc.z * w10.y;
                    ax += fc.w * w11.x; ay += fc.w * w11.y;
                    ax += fd.x * w12.x; ay += fd.x * w12.y;
                    ax += fd.y * w13.x; ay += fd.y * w13.y;
                    ax += fd.z * w14.x; ay += fd.z * w14.y;
                    ax += fd.w * w15.x; ay += fd.w * w15.y;
                    acc[j].x = ax; acc[j].y = ay;
                }
            }
        }

        #pragma unroll
        for (int j = 0; j < VPW; ++j) {
            int v = vb + j;
            if (v < N) {
                float2* op = (float2*)(out + (size_t)v * 64);
                op[lane] = acc[j];
            }
        }
    }
}

extern "C" void kernel_launch(void* const* d_in, const int* in_sizes, int n_in,
                              void* d_out, int out_size)
{
    const float* feat   = (const float*)d_in[0];  // [N, 64]
    const float* weight = (const float*)d_in[1];  // [4, 27, 16, 16]
    const float* bias   = (const float*)d_in[2];  // [64]
    const int*   nb     = (const int*)d_in[3];    // [N, 27]
    float* out = (float*)d_out;

    int N = in_sizes[0] / 64;

    // Idempotent, enqueues no work; safe under graph capture.
    cudaFuncSetAttribute(subm_conv_v8,
                         cudaFuncAttributeMaxDynamicSharedMemorySize, SMEM_BYTES);

    const int blocks = 304;     // 2 CTAs x 110.8KB smem per SM on 152 SMs
    const int threads = 256;
    const int warps = blocks * (threads / 32);
    int total_iters = (N + VPW - 1) / VPW;
    int iters_per_warp = (total_iters + warps - 1) / warps;

    subm_conv_v8<<<blocks, threads, SMEM_BYTES>>>(feat, weight, bias, nb,
                                                  out, N, iters_per_warp,
                                                  total_iters);
    (void)n_in; (void)out_size;
}

// round 3
// speedup vs baseline: 1.0526x; 1.0171x over previous
#include <cuda_runtime.h>
#include <cuda_bf16.h>

// Grouped submanifold sparse conv, N=400000, C_IN=C_OUT=64, GROUPS=4, K=27.
// R3: R2's 8-voxel weight-reuse + batched gather loads for MLP.
// Per union-offset k: process bodies in two halves of 4; within a half, all
// active bodies' feature loads are issued before any compute (MLP 4-16),
// weights LDS'd once per k under the LDG shadow, then FFMA blocks.
// Per-lane activity byte 'am' (lane k holds 8-voxel mask for offset k)
// replaces 8 ballots + 8 mask registers.

#define GROUPS 4
#define KOFF   27
#define CPG    16
#define WK     (CPG * CPG)      // 256 floats per (g,k)
#define WG_RAW (KOFF * WK)      // 6912 floats per group
#define PG     (WG_RAW + 16)    // padded group stride (16-bank shift per group)
#define SMEM_FLOATS (GROUPS * PG)
#define SMEM_BYTES  (SMEM_FLOATS * 4)
#define VPW 8

#define FFMA16(ACC, F, W)                                             \
    do {                                                              \
        float ax_ = (ACC).x, ay_ = (ACC).y;                           \
        ax_ += (F)[0].x * (W)[0].x;   ay_ += (F)[0].x * (W)[0].y;     \
        ax_ += (F)[0].y * (W)[1].x;   ay_ += (F)[0].y * (W)[1].y;     \
        ax_ += (F)[0].z * (W)[2].x;   ay_ += (F)[0].z * (W)[2].y;     \
        ax_ += (F)[0].w * (W)[3].x;   ay_ += (F)[0].w * (W)[3].y;     \
        ax_ += (F)[1].x * (W)[4].x;   ay_ += (F)[1].x * (W)[4].y;     \
        ax_ += (F)[1].y * (W)[5].x;   ay_ += (F)[1].y * (W)[5].y;     \
        ax_ += (F)[1].z * (W)[6].x;   ay_ += (F)[1].z * (W)[6].y;     \
        ax_ += (F)[1].w * (W)[7].x;   ay_ += (F)[1].w * (W)[7].y;     \
        ax_ += (F)[2].x * (W)[8].x;   ay_ += (F)[2].x * (W)[8].y;     \
        ax_ += (F)[2].y * (W)[9].x;   ay_ += (F)[2].y * (W)[9].y;     \
        ax_ += (F)[2].z * (W)[10].x;  ay_ += (F)[2].z * (W)[10].y;    \
        ax_ += (F)[2].w * (W)[11].x;  ay_ += (F)[2].w * (W)[11].y;    \
        ax_ += (F)[3].x * (W)[12].x;  ay_ += (F)[3].x * (W)[12].y;    \
        ax_ += (F)[3].y * (W)[13].x;  ay_ += (F)[3].y * (W)[13].y;    \
        ax_ += (F)[3].z * (W)[14].x;  ay_ += (F)[3].z * (W)[14].y;    \
        ax_ += (F)[3].w * (W)[15].x;  ay_ += (F)[3].w * (W)[15].y;    \
        (ACC).x = ax_; (ACC).y = ay_;                                 \
    } while (0)

__global__ __launch_bounds__(256, 2)
void subm_conv_v8p(const float* __restrict__ feat,
                   const float* __restrict__ weight,
                   const float* __restrict__ bias,
                   const int* __restrict__ nb,
                   float* __restrict__ out,
                   int N, int iters_per_warp, int total_iters)
{
    extern __shared__ float sw[];
    for (int i = threadIdx.x; i < GROUPS * WG_RAW; i += blockDim.x) {
        int g = i / WG_RAW;
        int r = i - g * WG_RAW;
        sw[g * PG + r] = weight[i];
    }
    __syncthreads();

    const int lane = threadIdx.x & 31;
    const int gwarp = (blockIdx.x * blockDim.x + threadIdx.x) >> 5;
    const int g    = lane >> 3;
    const int co0  = (lane & 7) * 2;
    const float bx = bias[2 * lane];
    const float by = bias[2 * lane + 1];
    const float* wgbase = sw + g * PG + co0;

    int it0 = gwarp * iters_per_warp;
    int it1 = it0 + iters_per_warp;
    if (it1 > total_iters) it1 = total_iters;

    for (int it = it0; it < it1; ++it) {
        const int vb = it * VPW;

        // Lane k (<27) loads offset-k neighbor index for each of 8 voxels.
        int idx[VPW];
        #pragma unroll
        for (int j = 0; j < VPW; ++j) {
            int v = vb + j;
            idx[j] = (lane < KOFF && v < N) ? nb[(size_t)v * KOFF + lane] : -1;
        }
        // Per-lane activity byte: bit j = voxel j active at this lane's offset.
        unsigned am = 0;
        #pragma unroll
        for (int j = 0; j < VPW; ++j) am |= (idx[j] >= 0 ? 1u : 0u) << j;
        unsigned uni = __ballot_sync(0xffffffffu, am != 0);

        float2 acc[VPW];
        #pragma unroll
        for (int j = 0; j < VPW; ++j) acc[j] = make_float2(bx, by);

        while (uni) {
            const int k = __ffs(uni) - 1;
            uni &= uni - 1;
            const unsigned jm = __shfl_sync(0xffffffffu, am, k);
            const float2* wp = (const float2*)(wgbase + k * WK);

            float4 fr[4][4];

            // ---- half A (voxels 0..3): batched loads, then weights, then FFMA
            const bool haveA = (jm & 0xFu) != 0;
            if (haveA) {
                #pragma unroll
                for (int j = 0; j < 4; ++j) {
                    if ((jm >> j) & 1u) {
                        int ni = __shfl_sync(0xffffffffu, idx[j], k);
                        const float4* fp = (const float4*)feat + (size_t)ni * 16 + g * 4;
                        fr[j][0] = fp[0]; fr[j][1] = fp[1];
                        fr[j][2] = fp[2]; fr[j][3] = fp[3];
                    }
                }
            }

            // Weight column pair for this k (16 x LDS.64, under LDG shadow).
            float2 w[16];
            #pragma unroll
            for (int i = 0; i < 16; ++i) w[i] = wp[i * 8];

            if (haveA) {
                #pragma unroll
                for (int j = 0; j < 4; ++j)
                    if ((jm >> j) & 1u) FFMA16(acc[j], fr[j], w);
            }

            // ---- half B (voxels 4..7): reuse fr registers
            if (jm & 0xF0u) {
                #pragma unroll
                for (int j = 4; j < 8; ++j) {
                    if ((jm >> j) & 1u) {
                        int ni = __shfl_sync(0xffffffffu, idx[j], k);
                        const float4* fp = (const float4*)feat + (size_t)ni * 16 + g * 4;
                        fr[j - 4][0] = fp[0]; fr[j - 4][1] = fp[1];
                        fr[j - 4][2] = fp[2]; fr[j - 4][3] = fp[3];
                    }
                }
                #pragma unroll
                for (int j = 4; j < 8; ++j)
                    if ((jm >> j) & 1u) FFMA16(acc[j], fr[j - 4], w);
            }
        }

        #pragma unroll
        for (int j = 0; j < VPW; ++j) {
            int v = vb + j;
            if (v < N) {
                float2* op = (float2*)(out + (size_t)v * 64);
                op[lane] = acc[j];
            }
        }
    }
}

extern "C" void kernel_launch(void* const* d_in, const int* in_sizes, int n_in,
                              void* d_out, int out_size)
{
    const float* feat   = (const float*)d_in[0];  // [N, 64]
    const float* weight = (const float*)d_in[1];  // [4, 27, 16, 16]
    const float* bias   = (const float*)d_in[2];  // [64]
    const int*   nb     = (const int*)d_in[3];    // [N, 27]
    float* out = (float*)d_out;

    int N = in_sizes[0] / 64;

    // Idempotent, enqueues no work; safe under graph capture.
    cudaFuncSetAttribute(subm_conv_v8p,
                         cudaFuncAttributeMaxDynamicSharedMemorySize, SMEM_BYTES);

    const int blocks = 304;     // 2 CTAs/SM (smem 110.8KB x2 fits 228KB)
    const int threads = 256;
    const int warps = blocks * (threads / 32);
    int total_iters = (N + VPW - 1) / VPW;
    int iters_per_warp = (total_iters + warps - 1) / warps;

    subm_conv_v8p<<<blocks, threads, SMEM_BYTES>>>(feat, weight, bias, nb,
                                                   out, N, iters_per_warp,
                                                   total_iters);
    (void)n_in; (void)out_size;
}